// round 10
// baseline (speedup 1.0000x reference)
#include <cuda_runtime.h>
#include <cstdint>

// Problem constants
#define BATCH 32
#define NEXP 8
#define CIN 64
#define COUT 64
#define HW 25600            // 160*160
#define NTW 16              // pixels per warp-tile
#define ITERS 16            // tiles per warp -> 256-px strip
#define XSW 16              // smem row stride in floats (XOR-swizzled)
#define TILEF (CIN * XSW)   // 1024 floats = 4KB per stage
#define NBUF 2
#define WARPF (NBUF * TILEF)        // 2048 floats per warp
// static smem: 4 warps * 8KB = 32KB -> 5 CTAs/SM

// Fragment-packed, TF32-rounded W: g_W2[b][(k*4+m)*32 + lane] =
//   {W[m16+g][k8+t], W[m16+8+g][k8+t], W[m16+g][k8+t+4], W[m16+8+g][k8+t+4]}
__device__ float4 g_W2[BATCH * 1024];

__device__ __forceinline__ uint32_t f2tf32(float f) {
    uint32_t r;
    asm("cvt.rna.tf32.f32 %0, %1;" : "=r"(r) : "f"(f));
    return r;
}
__device__ __forceinline__ float tf32r(float f) { return __uint_as_float(f2tf32(f)); }

__device__ __forceinline__ void cp_async16(float* dst_smem, const float* src_gmem) {
    uint32_t d = (uint32_t)__cvta_generic_to_shared(dst_smem);
    asm volatile("cp.async.cg.shared.global [%0], [%1], 16;\n" :: "r"(d), "l"(src_gmem));
}
__device__ __forceinline__ void cp_commit() {
    asm volatile("cp.async.commit_group;\n" ::: "memory");
}
template<int N> __device__ __forceinline__ void cp_wait() {
    asm volatile("cp.async.wait_group %0;\n" :: "n"(N) : "memory");
}

// Kernel 1: build fragment-packed W with (1+3.38e-4) bias pre-scale + tf32-RNA.
// Scale cancels first-order truncation bias of raw-fp32 X bits in the tf32 MMA.
__global__ void lla_weights_kernel(const float* __restrict__ alpha,
                                   const float* __restrict__ ke) {
    const int b = blockIdx.x;
    __shared__ float a_s[NEXP];
    if (threadIdx.x < NEXP) a_s[threadIdx.x] = alpha[b * NEXP + threadIdx.x];
    __syncthreads();
#pragma unroll
    for (int ent = 0; ent < 4; ent++) {
        int id = ent * 256 + threadIdx.x;   // 0..1023
        int l  = id & 31;
        int km = id >> 5;                   // k*4 + m
        int m  = km & 3, k = km >> 2;
        int g  = l >> 2, t = l & 3;
        int r0 = m * 16 + g, r1 = r0 + 8;
        int c0 = k * 8 + t,  c1 = c0 + 4;
        float s00 = 0.f, s10 = 0.f, s01 = 0.f, s11 = 0.f;
#pragma unroll
        for (int e = 0; e < NEXP; e++) {
            const float* kb = ke + e * COUT * CIN;
            float a = a_s[e];
            s00 = fmaf(a, kb[r0 * 64 + c0], s00);
            s10 = fmaf(a, kb[r1 * 64 + c0], s10);
            s01 = fmaf(a, kb[r0 * 64 + c1], s01);
            s11 = fmaf(a, kb[r1 * 64 + c1], s11);
        }
        g_W2[b * 1024 + id] = make_float4(
            tf32r(s00 * 1.000338f), tf32r(s10 * 1.000338f),
            tf32r(s01 * 1.000338f), tf32r(s11 * 1.000338f));
    }
}

// Kernel 2: warp-autonomous tf32-mma pipelines, 5 CTAs/SM (20 warps).
// 4 warps/CTA; each warp: private 2-stage cp.async ring over a 256-px strip,
// M=64 x N=16 per tile. A-fragments via L1-hot LDG.128 from g_W2.
__global__ __launch_bounds__(128, 5)
void lla_conv_kernel(const float* __restrict__ x, float* __restrict__ out) {
    __shared__ float smem[4 * WARPF];   // 32KB static

    const int b    = blockIdx.y;
    const int tid  = threadIdx.x;
    const int lane = tid & 31;
    const int warp = tid >> 5;
    const int g    = lane >> 2;     // 0..7
    const int tig  = lane & 3;      // 0..3
    const int sb   = tig >> 1;      // swizzle bit for B-row reads

    const float*  xb  = x   + (size_t)b * CIN  * HW;
    float*        ob  = out + (size_t)b * COUT * HW;
    const float4* wf  = g_W2 + b * 1024 + lane;
    float* const  ring = smem + warp * WARPF;
    const int pw = (blockIdx.x * 4 + warp) * (NTW * ITERS);

    // ---- Prologue: tiles 0,1 into stages 0,1 ----
#pragma unroll
    for (int t = 0; t < 2; t++) {
#pragma unroll
        for (int j = 0; j < 8; j++) {
            int id  = lane + 32 * j;            // 0..255
            int row = id >> 2;                  // 0..63
            int q   = id & 3;                   // 16B chunk
            int qs  = q ^ (((row >> 1) & 1) << 1);
            cp_async16(ring + t * TILEF + row * XSW + qs * 4,
                       xb + row * HW + pw + t * NTW + q * 4);
        }
        cp_commit();
    }

    for (int it = 0; it < ITERS; it++) {
        float* const cur = ring + (it & 1) * TILEF;
        const int p0 = pw + it * NTW;

        if (it < ITERS - 1) cp_wait<1>(); else cp_wait<0>();
        __syncwarp();

        // ---- Compute: 4 m-subtiles x 2 n-subtiles x 8 k-steps ----
        float acc[4][2][4];
#pragma unroll
        for (int m = 0; m < 4; m++)
#pragma unroll
            for (int n = 0; n < 2; n++) {
                acc[m][n][0] = 0.f; acc[m][n][1] = 0.f;
                acc[m][n][2] = 0.f; acc[m][n][3] = 0.f;
            }
#pragma unroll
        for (int k = 0; k < 8; k++) {
            const int r0 = (k * 8 + tig)     * XSW;
            const int r1 = (k * 8 + 4 + tig) * XSW;
            const int c0 = g       ^ (sb << 3);
            const int c1 = (8 + g) ^ (sb << 3);
            uint32_t b00 = __float_as_uint(cur[r0 + c0]);
            uint32_t b01 = __float_as_uint(cur[r1 + c0]);
            uint32_t b10 = __float_as_uint(cur[r0 + c1]);
            uint32_t b11 = __float_as_uint(cur[r1 + c1]);
#pragma unroll
            for (int m = 0; m < 4; m++) {
                float4 a = __ldg(wf + (k * 4 + m) * 32);
                uint32_t a0 = __float_as_uint(a.x), a1 = __float_as_uint(a.y);
                uint32_t a2 = __float_as_uint(a.z), a3 = __float_as_uint(a.w);
                asm volatile(
                    "mma.sync.aligned.m16n8k8.row.col.f32.tf32.tf32.f32 "
                    "{%0,%1,%2,%3}, {%4,%5,%6,%7}, {%8,%9}, {%0,%1,%2,%3};\n"
                    : "+f"(acc[m][0][0]), "+f"(acc[m][0][1]),
                      "+f"(acc[m][0][2]), "+f"(acc[m][0][3])
                    : "r"(a0), "r"(a1), "r"(a2), "r"(a3), "r"(b00), "r"(b01));
                asm volatile(
                    "mma.sync.aligned.m16n8k8.row.col.f32.tf32.tf32.f32 "
                    "{%0,%1,%2,%3}, {%4,%5,%6,%7}, {%8,%9}, {%0,%1,%2,%3};\n"
                    : "+f"(acc[m][1][0]), "+f"(acc[m][1][1]),
                      "+f"(acc[m][1][2]), "+f"(acc[m][1][3])
                    : "r"(a0), "r"(a1), "r"(a2), "r"(a3), "r"(b10), "r"(b11));
            }
        }

        // ---- Prefetch tile it+2 into the stage just consumed ----
        if (it + 2 < ITERS) {
            float* const nxt = cur;             // stage (it+2)&1 == it&1
            const int pn = p0 + 2 * NTW;
#pragma unroll
            for (int j = 0; j < 8; j++) {
                int id  = lane + 32 * j;
                int row = id >> 2;
                int q   = id & 3;
                int qs  = q ^ (((row >> 1) & 1) << 1);
                cp_async16(nxt + row * XSW + qs * 4, xb + row * HW + pn + q * 4);
            }
            cp_commit();
        }

        // ---- Streaming stores: full 32B sectors across the warp ----
#pragma unroll
        for (int m = 0; m < 4; m++)
#pragma unroll
            for (int n = 0; n < 2; n++) {
                const int c = p0 + n * 8 + 2 * tig;
                float2 v0 = make_float2(acc[m][n][0], acc[m][n][1]);
                float2 v1 = make_float2(acc[m][n][2], acc[m][n][3]);
                __stcs(reinterpret_cast<float2*>(ob + (size_t)(m * 16 + g)     * HW + c), v0);
                __stcs(reinterpret_cast<float2*>(ob + (size_t)(m * 16 + 8 + g) * HW + c), v1);
            }
    }
}

extern "C" void kernel_launch(void* const* d_in, const int* in_sizes, int n_in,
                              void* d_out, int out_size) {
    const float* x     = (const float*)d_in[0];   // [32,64,160,160]
    const float* alpha = (const float*)d_in[1];   // [32,8]
    const float* ke    = (const float*)d_in[2];   // [8,64,64,1,1]
    float*       out   = (float*)d_out;           // [32,64,160,160]

    lla_weights_kernel<<<BATCH, 256>>>(alpha, ke);

    dim3 grid(HW / (4 * NTW * ITERS), BATCH);     // (25, 32)
    lla_conv_kernel<<<grid, 128>>>(x, out);
}